// round 17
// baseline (speedup 1.0000x reference)
#include <cuda_runtime.h>
#include <cuda_bf16.h>
#include <cuda_fp16.h>
#include <cstdint>

// Problem constants
#define BATCH   8
#define SEQ     1024
#define DIM     768
#define HEADS   12
#define HDIM    64
#define INNER   768
#define TRIPLE  2304
#define SCALE   0.125f

typedef __half f16;

// ---------------- static scratch ----------------
__device__ __align__(128) f16 g_e[(size_t)BATCH * HEADS * SEQ * SEQ];   // E = exp(S)/16
__device__ __align__(128) f16 g_rinv[(size_t)BATCH * SEQ * SEQ];        // 1/sum_h E

__device__ __align__(128) f16 g_x16[BATCH * SEQ * DIM];     // x (fp16)
__device__ __align__(128) f16 g_wq16[TRIPLE * DIM];         // transposed
__device__ __align__(128) f16 g_wo16[DIM * INNER];          // transposed
__device__ __align__(128) f16 g_o16[BATCH * SEQ * INNER];   // attention out (fp16)

__device__ __align__(128) f16 g_q16[BATCH * HEADS * SEQ * HDIM];    // Q (fp16, pre-scaled)
__device__ __align__(128) f16 g_k16[BATCH * HEADS * SEQ * HDIM];    // K (fp16)
__device__ __align__(128) f16 g_v16[BATCH * HEADS * SEQ * HDIM];    // V (fp16)

// ================= helpers =================
__device__ __forceinline__ uint32_t smem_to_u32(const void* p) {
    uint32_t a;
    asm("{ .reg .u64 t; cvta.to.shared.u64 t, %1; cvt.u32.u64 %0, t; }"
        : "=r"(a) : "l"(p));
    return a;
}
// swizzle for [rows x 32 f16] tiles (64B rows)
__device__ __forceinline__ uint32_t swz(uint32_t r, uint32_t c) {
    return (r * 4 + (c ^ ((r >> 1) & 3))) * 16;
}
// swizzle for [rows x 64 f16] tiles (128B rows), chunk c in [0,8)
__device__ __forceinline__ uint32_t swz128(uint32_t r, uint32_t c) {
    return r * 128 + ((c ^ (r & 7)) << 4);
}
__device__ __forceinline__ void ldmatrix_x4(uint32_t& r0, uint32_t& r1,
                                            uint32_t& r2, uint32_t& r3,
                                            uint32_t addr) {
    asm volatile("ldmatrix.sync.aligned.m8n8.x4.shared.b16 {%0,%1,%2,%3}, [%4];"
                 : "=r"(r0), "=r"(r1), "=r"(r2), "=r"(r3) : "r"(addr));
}
__device__ __forceinline__ void ldmatrix_x4_trans(uint32_t& r0, uint32_t& r1,
                                                  uint32_t& r2, uint32_t& r3,
                                                  uint32_t addr) {
    asm volatile("ldmatrix.sync.aligned.m8n8.x4.trans.shared.b16 {%0,%1,%2,%3}, [%4];"
                 : "=r"(r0), "=r"(r1), "=r"(r2), "=r"(r3) : "r"(addr));
}
__device__ __forceinline__ void mma_f16(float* c, const uint32_t* a,
                                        uint32_t b0, uint32_t b1) {
    asm volatile("mma.sync.aligned.m16n8k16.row.col.f32.f16.f16.f32 "
                 "{%0,%1,%2,%3}, {%4,%5,%6,%7}, {%8,%9}, {%0,%1,%2,%3};"
                 : "+f"(c[0]), "+f"(c[1]), "+f"(c[2]), "+f"(c[3])
                 : "r"(a[0]), "r"(a[1]), "r"(a[2]), "r"(a[3]),
                   "r"(b0), "r"(b1));
}
__device__ __forceinline__ uint32_t hmul2u(uint32_t a, uint32_t b) {
    __half2 r = __hmul2(*(__half2*)&a, *(__half2*)&b);
    return *(uint32_t*)&r;
}
#define CP_ASYNC16(sa, g) \
    asm volatile("cp.async.cg.shared.global [%0], [%1], 16;" :: "r"(sa), "l"(g))
#define CP_COMMIT() asm volatile("cp.async.commit_group;" ::: "memory")
#define CP_WAIT1()  asm volatile("cp.async.wait_group 1;" ::: "memory")
#define CP_WAIT0()  asm volatile("cp.async.wait_group 0;" ::: "memory")

__device__ __forceinline__ float fast_exp_s(float x) {
    const float LOG2E = 1.4426950408889634f;
    const float MAGIC = 12582912.0f;
    float z = fmaf(x, LOG2E, MAGIC);
    int   e = __float_as_int(z) - 0x4B400000;
    float i = z - MAGIC;
    float f = fmaf(x, LOG2E, -i);
    float p = 1.5403531e-4f;
    p = fmaf(p, f, 1.3333558e-3f);
    p = fmaf(p, f, 9.6181291e-3f);
    p = fmaf(p, f, 5.5504109e-2f);
    p = fmaf(p, f, 2.4022651e-1f);
    p = fmaf(p, f, 6.9314718e-1f);
    p = fmaf(p, f, 1.0f);
    return __int_as_float(__float_as_int(p) + ((e - 4) << 23));
}

// =========================================================================
// Prep kernels
// =========================================================================
__global__ __launch_bounds__(256) void cvt_f16_kernel(
    const float* __restrict__ in, f16* __restrict__ outp, int n4)
{
    int i = blockIdx.x * 256 + threadIdx.x;
    if (i >= n4) return;
    float4 v = ((const float4*)in)[i];
    __half2* O = (__half2*)outp;
    O[2 * i]     = __floats2half2_rn(v.x, v.y);
    O[2 * i + 1] = __floats2half2_rn(v.z, v.w);
}

__global__ __launch_bounds__(256) void transpose_f16_kernel(
    const float* __restrict__ in, f16* __restrict__ outp, int R, int C)
{
    __shared__ float t[32][33];
    const int tx = threadIdx.x, ty = threadIdx.y;
    const int bx = blockIdx.x, by = blockIdx.y;
    #pragma unroll
    for (int i = 0; i < 4; i++) {
        int r = by * 32 + ty + i * 8;
        t[ty + i * 8][tx] = in[(size_t)r * C + bx * 32 + tx];
    }
    __syncthreads();
    #pragma unroll
    for (int i = 0; i < 4; i++) {
        int c = bx * 32 + ty + i * 8;
        int r = by * 32 + tx;
        outp[(size_t)c * R + r] = __float2half_rn(t[tx][ty + i * 8]);
    }
}

// =========================================================================
// fp16 GEMM (single-A): C = A @ Bw^T. 128x128 tile, K-chunk 64, 3 stages,
// 1 barrier per 64-k. mode 0: qkv epilogue; mode 1: oproj + bias.
// =========================================================================
#define MATK_BYTES 16384                 // 128 rows x 64 f16
#define HMK_STG    (2 * MATK_BYTES)      // 32768
#define HMK_SMEM_BYTES (3 * HMK_STG)     // 98304

__global__ __launch_bounds__(256, 2) void hmma_f16_gemm_kernel(
    const f16* __restrict__ Aa, const f16* __restrict__ Bw,
    const float* __restrict__ bias, float* __restrict__ outp, int mode)
{
    extern __shared__ f16 sm[];
    const int tid = threadIdx.x, lane = tid & 31, wid = tid >> 5;
    const int wr = wid >> 1, wc = wid & 1;
    const int bn = blockIdx.x * 128, bm = blockIdx.y * 128;
    const uint32_t smem_base = smem_to_u32(sm);

    float acc[2][8][4] = {};

    const int lrow = tid >> 1;              // 0..127
    const int lcb = (tid & 1) * 4;          // chunk base 0 or 4

    auto issue = [&](int it, int s) {
        const int k0 = it * 64;
        const uint32_t sb = smem_base + (uint32_t)(s * HMK_STG);
        #pragma unroll
        for (int j = 0; j < 4; j++) {
            int c = lcb + j;
            CP_ASYNC16(sb + swz128(lrow, c),
                       Aa + (size_t)(bm + lrow) * DIM + k0 + c * 8);
            CP_ASYNC16(sb + MATK_BYTES + swz128(lrow, c),
                       Bw + (size_t)(bn + lrow) * DIM + k0 + c * 8);
        }
        CP_COMMIT();
    };

    const int NIT = DIM / 64;   // 12
    issue(0, 0);
    issue(1, 1);

    for (int it = 0; it < NIT; ++it) {
        if (it + 1 < NIT) { CP_WAIT1(); } else { CP_WAIT0(); }
        __syncthreads();
        if (it + 2 < NIT) issue(it + 2, (it + 2) % 3);

        const uint32_t sb = smem_base + (uint32_t)((it % 3) * HMK_STG);
        #pragma unroll
        for (int ks = 0; ks < 4; ks++) {
            const uint32_t c0 = ks * 2 + (lane >> 4);
            uint32_t ah[2][4], bf[4][4];
            #pragma unroll
            for (int mt = 0; mt < 2; mt++) {
                uint32_t r = wr * 32 + mt * 16 + (lane & 15);
                ldmatrix_x4(ah[mt][0], ah[mt][1], ah[mt][2], ah[mt][3],
                            sb + swz128(r, c0));
            }
            #pragma unroll
            for (int p = 0; p < 4; p++) {
                uint32_t r = wc * 64 + p * 16 + (lane & 15);
                ldmatrix_x4(bf[p][0], bf[p][1], bf[p][2], bf[p][3],
                            sb + MATK_BYTES + swz128(r, c0));
            }
            #pragma unroll
            for (int p = 0; p < 4; p++)
                #pragma unroll
                for (int mt = 0; mt < 2; mt++) {
                    mma_f16(acc[mt][2 * p + 0], ah[mt], bf[p][0], bf[p][2]);
                    mma_f16(acc[mt][2 * p + 1], ah[mt], bf[p][1], bf[p][3]);
                }
        }
    }

    // ---- epilogue ----
    #pragma unroll
    for (int mt = 0; mt < 2; mt++) {
        const int r = bm + wr * 32 + mt * 16 + (lane >> 2);
        #pragma unroll
        for (int nt = 0; nt < 8; nt++) {
            const int c = bn + wc * 64 + nt * 8 + 2 * (lane & 3);
            float2 v0 = make_float2(acc[mt][nt][0], acc[mt][nt][1]);
            float2 v1 = make_float2(acc[mt][nt][2], acc[mt][nt][3]);
            if (mode == 0) {
                int chunk = c / INNER;
                int e = c % INNER;
                int h = e >> 6, d = e & 63;
                int b0 = r >> 10, n0 = r & 1023;
                int r2 = r + 8;
                int b1 = r2 >> 10, n1 = r2 & 1023;
                size_t i0 = (((size_t)(b0 * HEADS + h) * SEQ) + n0) * HDIM + d;
                size_t i1 = (((size_t)(b1 * HEADS + h) * SEQ) + n1) * HDIM + d;
                f16* dst;
                if (chunk == 2)      dst = g_v16;
                else if (chunk == 1) dst = g_k16;
                else {
                    dst = g_q16;
                    v0.x *= SCALE; v0.y *= SCALE;
                    v1.x *= SCALE; v1.y *= SCALE;
                }
                *(__half2*)&dst[i0] = __floats2half2_rn(v0.x, v0.y);
                *(__half2*)&dst[i1] = __floats2half2_rn(v1.x, v1.y);
            } else {
                float2 bq = *(const float2*)&bias[c];
                v0.x += bq.x; v0.y += bq.y;
                v1.x += bq.x; v1.y += bq.y;
                *(float2*)&outp[(size_t)r * DIM + c] = v0;
                *(float2*)&outp[(size_t)(r + 8) * DIM + c] = v1;
            }
        }
    }
}

// =========================================================================
// Score (fused): one CTA per (b, n0, m0), all 12 heads; writes E and rinv.
// 3-stage head pipeline, ONE barrier per head.
// =========================================================================
#define SGS 72
#define S3_Q_BYTES (128 * SGS * 2)                 // 18432
#define S3_K_BYTES (64 * SGS * 2)                  // 9216
#define S3_STG (S3_Q_BYTES + S3_K_BYTES)           // 27648
#define S3_SMEM_BYTES (3 * S3_STG)                 // 82944

__global__ __launch_bounds__(256, 2) void score_hmma_kernel()
{
    extern __shared__ f16 smh[];
    const int tid = threadIdx.x, lane = tid & 31, wid = tid >> 5;
    const int wr = wid >> 1, wc = wid & 1;
    const int m0 = blockIdx.x * 64;
    const int n0 = blockIdx.y * 128;
    const int b  = blockIdx.z;
    const uint32_t smem_base = smem_to_u32(smh);

    auto issue = [&](int h, int s) {
        const size_t bh = (size_t)(b * HEADS + h);
        const f16* q = g_q16 + (bh * SEQ + n0) * HDIM;
        const f16* k = g_k16 + (bh * SEQ + m0) * HDIM;
        const uint32_t sb = smem_base + (uint32_t)(s * S3_STG);
        #pragma unroll
        for (int t = 0; t < 4; t++) {
            int i = tid + t * 256;
            int row = i >> 3, ch = i & 7;
            CP_ASYNC16(sb + (uint32_t)(row * SGS + ch * 8) * 2,
                       q + (size_t)row * HDIM + ch * 8);
        }
        #pragma unroll
        for (int t = 0; t < 2; t++) {
            int i = tid + t * 256;
            int row = i >> 3, ch = i & 7;
            CP_ASYNC16(sb + S3_Q_BYTES + (uint32_t)(row * SGS + ch * 8) * 2,
                       k + (size_t)row * HDIM + ch * 8);
        }
        CP_COMMIT();
    };

    issue(0, 0);
    issue(1, 1);

    float sumf[2][4][4] = {};

    for (int h = 0; h < HEADS; ++h) {
        if (h + 1 < HEADS) { CP_WAIT1(); } else { CP_WAIT0(); }
        __syncthreads();
        if (h + 2 < HEADS) issue(h + 2, (h + 2) % 3);

        const uint32_t sb = smem_base + (uint32_t)((h % 3) * S3_STG);
        const uint32_t kbse = sb + S3_Q_BYTES;

        float acc[2][4][4] = {};
        #pragma unroll
        for (int ks = 0; ks < 4; ks++) {
            const uint32_t col = ks * 16 + (lane >> 4) * 8;
            uint32_t aq[2][4], bf[2][4];
            #pragma unroll
            for (int mt = 0; mt < 2; mt++) {
                uint32_t r = wr * 32 + mt * 16 + (lane & 15);
                ldmatrix_x4(aq[mt][0], aq[mt][1], aq[mt][2], aq[mt][3],
                            sb + (r * SGS + col) * 2);
            }
            #pragma unroll
            for (int p = 0; p < 2; p++) {
                uint32_t r = wc * 32 + p * 16 + (lane & 15);
                ldmatrix_x4(bf[p][0], bf[p][1], bf[p][2], bf[p][3],
                            kbse + (r * SGS + col) * 2);
            }
            #pragma unroll
            for (int p = 0; p < 2; p++)
                #pragma unroll
                for (int mt = 0; mt < 2; mt++) {
                    mma_f16(acc[mt][2 * p + 0], aq[mt], bf[p][0], bf[p][2]);
                    mma_f16(acc[mt][2 * p + 1], aq[mt], bf[p][1], bf[p][3]);
                }
        }

        // epilogue: E for this head + accumulate head-sum (fp32)
        f16* ebase = g_e + ((size_t)(b * HEADS + h) * SEQ) * SEQ;
        #pragma unroll
        for (int mt = 0; mt < 2; mt++) {
            const int r = n0 + wr * 32 + mt * 16 + (lane >> 2);
            #pragma unroll
            for (int nt = 0; nt < 4; nt++) {
                const int c = m0 + wc * 32 + nt * 8 + 2 * (lane & 3);
                float e0 = fast_exp_s(acc[mt][nt][0]);
                float e1 = fast_exp_s(acc[mt][nt][1]);
                float e2 = fast_exp_s(acc[mt][nt][2]);
                float e3 = fast_exp_s(acc[mt][nt][3]);
                sumf[mt][nt][0] += e0; sumf[mt][nt][1] += e1;
                sumf[mt][nt][2] += e2; sumf[mt][nt][3] += e3;
                *(__half2*)&ebase[(size_t)r * SEQ + c] = __floats2half2_rn(e0, e1);
                *(__half2*)&ebase[(size_t)(r + 8) * SEQ + c] = __floats2half2_rn(e2, e3);
            }
        }
    }

    // rinv epilogue
    #pragma unroll
    for (int mt = 0; mt < 2; mt++) {
        const int r = n0 + wr * 32 + mt * 16 + (lane >> 2);
        #pragma unroll
        for (int nt = 0; nt < 4; nt++) {
            const int c = m0 + wc * 32 + nt * 8 + 2 * (lane & 3);
            *(__half2*)&g_rinv[((size_t)(b * SEQ + r)) * SEQ + c] =
                __floats2half2_rn(1.0f / sumf[mt][nt][0], 1.0f / sumf[mt][nt][1]);
            *(__half2*)&g_rinv[((size_t)(b * SEQ + r + 8)) * SEQ + c] =
                __floats2half2_rn(1.0f / sumf[mt][nt][2], 1.0f / sumf[mt][nt][3]);
        }
    }
}

// =========================================================================
// AV HMMA (fp16): O = (E*rinv) @ V, V single fp16. Unchanged from R16.
// =========================================================================
#define AVE_BYTES 8192
#define AVR_BYTES 8192
#define AVV_BYTES 4608
#define AV_STG_BYTES (AVE_BYTES + AVR_BYTES + AVV_BYTES)   // 20992
#define AV_SMEM_BYTES (3 * AV_STG_BYTES)                   // 62976
#define VGS 72

__global__ __launch_bounds__(256, 3) void av_hmma_kernel()
{
    extern __shared__ f16 smh[];
    const int tid = threadIdx.x, lane = tid & 31, wid = tid >> 5;
    const int wr = wid >> 1, wc = wid & 1;
    const int n0 = blockIdx.x * 128;
    const int bh = blockIdx.y;
    const int b = bh / HEADS, h = bh % HEADS;
    const uint32_t smem_base = smem_to_u32(smh);

    const f16* ep = g_e    + ((size_t)bh * SEQ + n0) * SEQ;
    const f16* rp = g_rinv + ((size_t)(b * SEQ + n0)) * SEQ;
    const f16* vp = g_v16  + (size_t)bh * SEQ * HDIM;

    float acc[2][4][4] = {};

    const int lr0 = tid >> 2, lr1 = (tid + 256) >> 2;
    const int lc = tid & 3;
    const int vrow_ld = tid >> 3, vch_ld = tid & 7;

    auto issue = [&](int it, int s) {
        const int k0 = it * 32;
        const uint32_t sb = smem_base + (uint32_t)(s * AV_STG_BYTES);
        CP_ASYNC16(sb + swz(lr0, lc), ep + (size_t)lr0 * SEQ + k0 + lc * 8);
        CP_ASYNC16(sb + swz(lr1, lc), ep + (size_t)lr1 * SEQ + k0 + lc * 8);
        CP_ASYNC16(sb + AVE_BYTES + swz(lr0, lc), rp + (size_t)lr0 * SEQ + k0 + lc * 8);
        CP_ASYNC16(sb + AVE_BYTES + swz(lr1, lc), rp + (size_t)lr1 * SEQ + k0 + lc * 8);
        CP_ASYNC16(sb + AVE_BYTES + AVR_BYTES + (uint32_t)(vrow_ld * VGS + vch_ld * 8) * 2,
                   vp + (size_t)(k0 + vrow_ld) * HDIM + vch_ld * 8);
        CP_COMMIT();
    };

    const int NIT = SEQ / 32;
    issue(0, 0);
    issue(1, 1);

    for (int it = 0; it < NIT; ++it) {
        if (it + 1 < NIT) { CP_WAIT1(); } else { CP_WAIT0(); }
        __syncthreads();
        if (it + 2 < NIT) issue(it + 2, (it + 2) % 3);

        const uint32_t sb = smem_base + (uint32_t)((it % 3) * AV_STG_BYTES);
        const uint32_t rvb = sb + AVE_BYTES;
        const uint32_t vb = rvb + AVR_BYTES;

        #pragma unroll
        for (int ks = 0; ks < 2; ks++) {
            const uint32_t c0 = ks * 2 + (lane >> 4);
            uint32_t a[2][4];
            #pragma unroll
            for (int mt = 0; mt < 2; mt++) {
                uint32_t r = wr * 32 + mt * 16 + (lane & 15);
                uint32_t rv[4];
                ldmatrix_x4(a[mt][0], a[mt][1], a[mt][2], a[mt][3],
                            sb + swz(r, c0));
                ldmatrix_x4(rv[0], rv[1], rv[2], rv[3],
                            rvb + swz(r, c0));
                #pragma unroll
                for (int j = 0; j < 4; j++) a[mt][j] = hmul2u(a[mt][j], rv[j]);
            }
            const uint32_t kb = ks * 16;
            #pragma unroll
            for (int nb = 0; nb < 2; nb++) {
                const uint32_t d0 = wc * 32 + nb * 16;
                uint32_t vrow = kb + (lane & 7) + ((lane >> 3) & 1) * 8;
                uint32_t vcol = d0 + (lane >> 4) * 8;
                uint32_t b0, b1, b2, b3;
                ldmatrix_x4_trans(b0, b1, b2, b3, vb + (vrow * VGS + vcol) * 2);
                const int nt0 = nb * 2, nt1 = nb * 2 + 1;
                #pragma unroll
                for (int mt = 0; mt < 2; mt++) {
                    mma_f16(acc[mt][nt0], a[mt], b0, b1);
                    mma_f16(acc[mt][nt1], a[mt], b2, b3);
                }
            }
        }
    }

    // epilogue: O -> single fp16 at [b, n, h*64+d]
    #pragma unroll
    for (int mt = 0; mt < 2; mt++) {
        const int r = n0 + wr * 32 + mt * 16 + (lane >> 2);
        #pragma unroll
        for (int nt = 0; nt < 4; nt++) {
            const int c = wc * 32 + nt * 8 + 2 * (lane & 3);
            size_t i0 = ((size_t)(b * SEQ + r)) * INNER + h * HDIM + c;
            size_t i1 = ((size_t)(b * SEQ + r + 8)) * INNER + h * HDIM + c;
            *(__half2*)&g_o16[i0] = __floats2half2_rn(acc[mt][nt][0], acc[mt][nt][1]);
            *(__half2*)&g_o16[i1] = __floats2half2_rn(acc[mt][nt][2], acc[mt][nt][3]);
        }
    }
}

// =========================================================================
extern "C" void kernel_launch(void* const* d_in, const int* in_sizes, int n_in,
                              void* d_out, int out_size)
{
    const float* x     = (const float*)d_in[0];
    const float* w_qkv = (const float*)d_in[1];
    const float* w_out = (const float*)d_in[2];
    const float* b_out = (const float*)d_in[3];
    float* out = (float*)d_out;

    cudaFuncSetAttribute(hmma_f16_gemm_kernel,
                         cudaFuncAttributeMaxDynamicSharedMemorySize, HMK_SMEM_BYTES);
    cudaFuncSetAttribute(score_hmma_kernel,
                         cudaFuncAttributeMaxDynamicSharedMemorySize, S3_SMEM_BYTES);
    cudaFuncSetAttribute(av_hmma_kernel,
                         cudaFuncAttributeMaxDynamicSharedMemorySize, AV_SMEM_BYTES);

    f16 *x16, *wq, *wo, *o16;
    cudaGetSymbolAddress((void**)&x16, g_x16);
    cudaGetSymbolAddress((void**)&wq,  g_wq16);
    cudaGetSymbolAddress((void**)&wo,  g_wo16);
    cudaGetSymbolAddress((void**)&o16, g_o16);

    // Prep
    {
        int n4 = BATCH * SEQ * DIM / 4;
        cvt_f16_kernel<<<(n4 + 255) / 256, 256>>>(x, x16, n4);
    }
    {
        dim3 grid(TRIPLE / 32, DIM / 32);
        transpose_f16_kernel<<<grid, dim3(32, 8)>>>(w_qkv, wq, DIM, TRIPLE);
    }
    {
        dim3 grid(DIM / 32, INNER / 32);
        transpose_f16_kernel<<<grid, dim3(32, 8)>>>(w_out, wo, INNER, DIM);
    }

    // K1: QKV projection (fp16 single-A, K-chunk 64, 3-stage)
    {
        dim3 grid(TRIPLE / 128, (BATCH * SEQ) / 128);
        hmma_f16_gemm_kernel<<<grid, 256, HMK_SMEM_BYTES>>>(x16, wq, nullptr, nullptr, 0);
    }
    // K2: scores + exp + head-sum -> E, rinv (fused, 3-stage, 1 barrier/head)
    {
        dim3 grid(SEQ / 64, SEQ / 128, BATCH);
        score_hmma_kernel<<<grid, 256, S3_SMEM_BYTES>>>();
    }
    // K3: O = (E*rinv) @ V (fp16 HMMA, V single)
    {
        dim3 grid(SEQ / 128, BATCH * HEADS);
        av_hmma_kernel<<<grid, 256, AV_SMEM_BYTES>>>();
    }
    // K4: output projection (fp16 single-A, K-chunk 64, 3-stage) + bias
    {
        dim3 grid(DIM / 128, (BATCH * SEQ) / 128);
        hmma_f16_gemm_kernel<<<grid, 256, HMK_SMEM_BYTES>>>(o16, wo, b_out, out, 1);
    }
}